// round 16
// baseline (speedup 1.0000x reference)
#include <cuda_runtime.h>
#include <cstdint>
#include <cstddef>

#define B_   128
#define C_   2048
#define HW_  196
#define ND_  32
#define NA_  1845

#define THREADS 128         // 4 warps
#define CK      256         // floats per k-chunk (1KB per W row)
#define NCHUNK  8           // 2048 / 256
#define ATILE   16          // answer rows per block (4 warps x 4 rows)

// Scratch for attended features (cudaMalloc is forbidden) — 1 MB, L2-hot.
__device__ __align__(1024) float g_att[B_ * C_];

// ---- dynamic smem layout (bytes) ----
// W bufs 3x16KB at 0 (NBUF=3, single barrier per stage). Control at 48KB.
// PADDED to 56KB: exactly 4 blocks/SM, capping the chip-wide live W
// footprint at 4*148*128KB = 75MB -- the verified L2-reread-safe regime
// (R4/R14 ~500MB vs R13's 95MB -> 613MB blowout).
#define SM_LIST 49152                     // int[128]
#define SM_CNT  (SM_LIST + 512)
#define SM_IS64 (SM_CNT + 4)
#define SM_TOT  57344                     // 56KB -> exactly 4 blocks/SM

// ---------------------------------------------------------------------------
// Kernel 1: attended[b][c] = (1/196) * sum_hw mask[b][hw] * features[b][c][hw]
// One warp per (b,c) row; at the LTS streaming cap — unchanged.
// ---------------------------------------------------------------------------
__global__ void __launch_bounds__(256) k_attend(const float* __restrict__ mask,
                                                const float* __restrict__ feat)
{
    int gw   = (blockIdx.x * 256 + threadIdx.x) >> 5;
    int lane = threadIdx.x & 31;
    if (gw >= B_ * C_) return;
    int b = gw >> 11;

    const float4* f  = (const float4*)(feat + (size_t)gw * HW_);
    const float4* mk = (const float4*)(mask + (size_t)b  * HW_);

    float4 a0 = f[lane], m0 = mk[lane];
    float s = a0.x * m0.x + a0.y * m0.y + a0.z * m0.z + a0.w * m0.w;
    if (lane < 17) {
        float4 a1 = f[lane + 32], m1 = mk[lane + 32];
        s += a1.x * m1.x + a1.y * m1.y + a1.z * m1.z + a1.w * m1.w;
    }
    #pragma unroll
    for (int o = 16; o; o >>= 1) s += __shfl_xor_sync(0xffffffffu, s, o);
    if (lane == 0) g_att[gw] = s * (1.0f / 196.0f);
}

// ---------------------------------------------------------------------------
// Helpers
// ---------------------------------------------------------------------------
__device__ __forceinline__ void fma2(unsigned long long& d,
                                     unsigned long long a,
                                     unsigned long long b)
{
    asm("fma.rn.f32x2 %0, %1, %2, %0;" : "+l"(d) : "l"(a), "l"(b));
}

__device__ __forceinline__ uint32_t smem_u32(const void* p) {
    uint32_t a;
    asm("{ .reg .u64 t; cvta.to.shared.u64 t, %1; cvt.u32.u64 %0, t; }"
        : "=r"(a) : "l"(p));
    return a;
}

__device__ __forceinline__ void cp16(uint32_t saddr, const void* gaddr) {
    asm volatile("cp.async.cg.shared.global [%0], [%1], 16;"
                 :: "r"(saddr), "l"(gaddr));
}
__device__ __forceinline__ void cp_commit() {
    asm volatile("cp.async.commit_group;");
}
template <int N>
__device__ __forceinline__ void cp_wait() {
    asm volatile("cp.async.wait_group %0;" :: "n"(N));
}

// ---------------------------------------------------------------------------
// Stage one W k-chunk: 16 rows x CK floats (16KB). 1024 f4 / 128 thr = 8 ea.
// ---------------------------------------------------------------------------
__device__ __forceinline__ void issueW(uint32_t smb,
                                       const float* __restrict__ Wg,
                                       int s, int tid)
{
    int k0 = s * CK;
    uint32_t wdst = smb + (s % 3) * 16384;
    #pragma unroll
    for (int i = 0; i < 8; i++) {
        int idx = i * 128 + tid;
        int row = idx >> 6, col = idx & 63;
        cp16(wdst + idx * 16, Wg + (size_t)row * C_ + k0 + col * 4);
    }
    cp_commit();
}

// ---------------------------------------------------------------------------
// One pass: 16 W rows x 4 samples/warp. W: NBUF=3 cp.async, ONE barrier per
// stage (issue k+2 after barrier k: buf (k+2)%3 was last read at stage k-1,
// whose readers all passed barrier k). X: register-prefetched via LDG from
// L2 one stage ahead (g_att is 1MB, hot; ~250cyc hidden under ~1300cyc stage).
// ---------------------------------------------------------------------------
__device__ __forceinline__ void run_pass(uint32_t smb, char* sm,
                                         const float* __restrict__ Wg,
                                         int tid, int lane, int warp,
                                         const int* bj,
                                         int a0c, int a0nom, int d,
                                         const float* __restrict__ bias,
                                         float* __restrict__ out)
{
    const ulonglong2* xp[4];
    #pragma unroll
    for (int j = 0; j < 4; j++)
        xp[j] = (const ulonglong2*)(g_att + (size_t)bj[j] * C_);

    unsigned long long acc[4][4];
    #pragma unroll
    for (int r = 0; r < 4; r++)
        #pragma unroll
        for (int j = 0; j < 4; j++) acc[r][j] = 0ull;

    // Group-entry barrier: first issueW below overwrites buf0/buf1 which the
    // PREVIOUS group's final stages may still be reading (no trailing barrier
    // after its last compute). Same WAR class as the R3/R10 bugs.
    __syncthreads();

    // Prefetch X for stage 0; stage W 0 and 1.
    ulonglong2 xc[8];                                  // [st*4 + j]
    #pragma unroll
    for (int st = 0; st < 2; st++)
        #pragma unroll
        for (int j = 0; j < 4; j++)
            xc[st * 4 + j] = xp[j][lane + st * 32];
    issueW(smb, Wg, 0, tid);
    issueW(smb, Wg, 1, tid);

    #pragma unroll
    for (int k = 0; k < NCHUNK; k++) {
        if (k + 1 < NCHUNK) cp_wait<1>(); else cp_wait<0>();
        __syncthreads();                               // stage k visible; WAR ok
        if (k + 2 < NCHUNK) issueW(smb, Wg, k + 2, tid);

        // Prefetch next stage's X (LDG, L2-hit) before consuming this stage.
        ulonglong2 xn[8];
        if (k + 1 < NCHUNK) {
            int cb = (k + 1) * 64;
            #pragma unroll
            for (int st = 0; st < 2; st++)
                #pragma unroll
                for (int j = 0; j < 4; j++)
                    xn[st * 4 + j] = xp[j][cb + lane + st * 32];
        }

        const float* Wb = (const float*)(sm + (k % 3) * 16384);
        #pragma unroll
        for (int st = 0; st < 2; st++) {               // CK/4 = 64 float4
            int c = lane + st * 32;
            ulonglong2 w[4];
            #pragma unroll
            for (int r = 0; r < 4; r++)
                w[r] = ((const ulonglong2*)(Wb + (warp * 4 + r) * CK))[c];
            #pragma unroll
            for (int j = 0; j < 4; j++) {
                #pragma unroll
                for (int r = 0; r < 4; r++) {
                    fma2(acc[r][j], w[r].x, xc[st * 4 + j].x);
                    fma2(acc[r][j], w[r].y, xc[st * 4 + j].y);
                }
            }
        }
        if (k + 1 < NCHUNK) {
            #pragma unroll
            for (int i = 0; i < 8; i++) xc[i] = xn[i];
        }
    }

    #pragma unroll
    for (int r = 0; r < 4; r++) {
        int a = a0c + warp * 4 + r;
        #pragma unroll
        for (int j = 0; j < 4; j++) {                  // padded j idempotent
            float v = __uint_as_float((unsigned)(acc[r][j] & 0xffffffffu))
                    + __uint_as_float((unsigned)(acc[r][j] >> 32));
            #pragma unroll
            for (int o = 16; o; o >>= 1) v += __shfl_xor_sync(0xffffffffu, v, o);
            if (lane == 0 && a >= a0nom)
                out[(size_t)bj[j] * NA_ + a] = v + bias[(size_t)d * NA_ + a];
        }
    }
}

// ---------------------------------------------------------------------------
// Kernel 2: grouped GEMM. Grid (116, 32); single uniform pass shape.
// ---------------------------------------------------------------------------
__global__ void __launch_bounds__(THREADS, 4) k_gemm(const void* __restrict__ inst_raw,
                                                     const float* __restrict__ W,
                                                     const float* __restrict__ bias,
                                                     float* __restrict__ out)
{
    extern __shared__ char sm[];
    uint32_t smb = smem_u32(sm);
    int* s_list = (int*)(sm + SM_LIST);
    int* s_cnt  = (int*)(sm + SM_CNT);
    int* s_is64 = (int*)(sm + SM_IS64);

    if (threadIdx.x == 0) {
        // Detect int64 vs int32 instance layout (values 0..31 => odd words 0).
        const unsigned* pw = (const unsigned*)inst_raw;
        unsigned orv = 0;
        for (int i = 1; i < 128; i += 2) orv |= pw[i];
        *s_is64 = (orv == 0) ? 1 : 0;
        *s_cnt  = 0;
    }
    __syncthreads();

    int d = blockIdx.y;
    {   // 128 threads scan all 128 instances
        int v = *s_is64 ? (int)((const long long*)inst_raw)[threadIdx.x]
                        : ((const int*)inst_raw)[threadIdx.x];
        if (v == d) {
            int p = atomicAdd(s_cnt, 1);
            s_list[p] = threadIdx.x;
        }
    }
    __syncthreads();

    int m = *s_cnt;
    if (m == 0) return;                                // unused descriptor

    int tid  = threadIdx.x;
    int lane = tid & 31;
    int warp = tid >> 5;
    int a0nom = blockIdx.x * ATILE;
    int a0c   = a0nom > NA_ - ATILE ? NA_ - ATILE : a0nom;
    const float* W0 = W + ((size_t)d * NA_ + a0c) * C_;

    // s_list is written once above and never modified -> bj reads are safe
    // at any point (no cross-pass snapshot hazards).
    for (int mbase = 0; mbase < m; mbase += 4) {
        int mc = m - mbase; if (mc > 4) mc = 4;
        int bj[4];
        #pragma unroll
        for (int j = 0; j < 4; j++)
            bj[j] = s_list[mbase + (j < mc ? j : mc - 1)];

        run_pass(smb, sm, W0, tid, lane, warp, bj, a0c, a0nom, d, bias, out);
    }
}

// ---------------------------------------------------------------------------
// Inputs (metadata order): mask f32[128,1,14,14], features f32[128,2048,14,14],
// instance int[128], W f32[32,1845,2048], b f32[32,1845]. Output f32[128,1845].
// ---------------------------------------------------------------------------
extern "C" void kernel_launch(void* const* d_in, const int* in_sizes, int n_in,
                              void* d_out, int out_size)
{
    const float* mask = (const float*)d_in[0];
    const float* feat = (const float*)d_in[1];
    const void*  inst = d_in[2];
    const float* W    = (const float*)d_in[3];
    const float* bias = (const float*)d_in[4];
    float* out = (float*)d_out;

    int blocks1 = (B_ * C_) / 8;                       // warp per (b,c) row
    k_attend<<<blocks1, 256>>>(mask, feat);

    cudaFuncSetAttribute(k_gemm, cudaFuncAttributeMaxDynamicSharedMemorySize,
                         SM_TOT);
    dim3 g2((NA_ + ATILE - 1) / ATILE, ND_);           // (116, 32)
    k_gemm<<<g2, THREADS, SM_TOT>>>(inst, W, bias, out);
}

// round 17
// speedup vs baseline: 1.0307x; 1.0307x over previous
#include <cuda_runtime.h>
#include <cstdint>
#include <cstddef>

#define B_   128
#define C_   2048
#define HW_  196
#define ND_  32
#define NA_  1845

#define THREADS 128         // 4 warps
#define CK      256         // floats per k-chunk (1KB per W row)
#define NCHUNK  8           // 2048 / 256
#define ATILE   16          // answer rows per block (4 warps x 4 rows)

// Scratch for attended features (cudaMalloc is forbidden) — 1 MB, L2-hot.
__device__ __align__(1024) float g_att[B_ * C_];

// ---- dynamic smem layout (bytes) ----
// W bufs 3x16KB at 0, X bufs 3x4KB at 48KB, control at 60KB. ~61KB/block ->
// exactly 3 blocks/SM. Live W footprint 3*148*128KB = 57MB (well inside the
// <=75MB L2-reread-safe regime verified in R4/R14 vs R13).
// In-flight DRAM bytes: 2 stages x 20KB x 3 blocks = 120KB/SM (> R6's 108KB,
// the best-rate config measured).
#define X_OFF   49152
#define SM_LIST 61440                     // int[128]
#define SM_CNT  (SM_LIST + 512)
#define SM_IS64 (SM_CNT + 4)
#define SM_TOT  (SM_IS64 + 4)             // ~60.5KB -> 3 blocks/SM

// ---------------------------------------------------------------------------
// Kernel 1: attended[b][c] = (1/196) * sum_hw mask[b][hw] * features[b][c][hw]
// One warp per (b,c) row; at the streaming cap — unchanged.
// ---------------------------------------------------------------------------
__global__ void __launch_bounds__(256) k_attend(const float* __restrict__ mask,
                                                const float* __restrict__ feat)
{
    int gw   = (blockIdx.x * 256 + threadIdx.x) >> 5;
    int lane = threadIdx.x & 31;
    if (gw >= B_ * C_) return;
    int b = gw >> 11;

    const float4* f  = (const float4*)(feat + (size_t)gw * HW_);
    const float4* mk = (const float4*)(mask + (size_t)b  * HW_);

    float4 a0 = f[lane], m0 = mk[lane];
    float s = a0.x * m0.x + a0.y * m0.y + a0.z * m0.z + a0.w * m0.w;
    if (lane < 17) {
        float4 a1 = f[lane + 32], m1 = mk[lane + 32];
        s += a1.x * m1.x + a1.y * m1.y + a1.z * m1.z + a1.w * m1.w;
    }
    #pragma unroll
    for (int o = 16; o; o >>= 1) s += __shfl_xor_sync(0xffffffffu, s, o);
    if (lane == 0) g_att[gw] = s * (1.0f / 196.0f);
}

// ---------------------------------------------------------------------------
// Helpers
// ---------------------------------------------------------------------------
__device__ __forceinline__ void fma2(unsigned long long& d,
                                     unsigned long long a,
                                     unsigned long long b)
{
    asm("fma.rn.f32x2 %0, %1, %2, %0;" : "+l"(d) : "l"(a), "l"(b));
}

__device__ __forceinline__ uint32_t smem_u32(const void* p) {
    uint32_t a;
    asm("{ .reg .u64 t; cvta.to.shared.u64 t, %1; cvt.u32.u64 %0, t; }"
        : "=r"(a) : "l"(p));
    return a;
}

__device__ __forceinline__ void cp16(uint32_t saddr, const void* gaddr) {
    asm volatile("cp.async.cg.shared.global [%0], [%1], 16;"
                 :: "r"(saddr), "l"(gaddr));
}
__device__ __forceinline__ void cp_commit() {
    asm volatile("cp.async.commit_group;");
}
template <int N>
__device__ __forceinline__ void cp_wait() {
    asm volatile("cp.async.wait_group %0;" :: "n"(N));
}

// ---------------------------------------------------------------------------
// Stage one k-chunk: W 16 rows x CK (16KB, 8 cp16/thr) + X 4 rows x CK
// (4KB, 2 cp16/thr) into buf s%3. One commit group per stage.
// ---------------------------------------------------------------------------
__device__ __forceinline__ void issue_stage(uint32_t smb,
                                            const float* __restrict__ Wg,
                                            int s, int tid, const int* bj)
{
    int k0 = s * CK, buf = s % 3;
    uint32_t wdst = smb + buf * 16384;
    #pragma unroll
    for (int i = 0; i < 8; i++) {
        int idx = i * 128 + tid;
        int row = idx >> 6, col = idx & 63;
        cp16(wdst + idx * 16, Wg + (size_t)row * C_ + k0 + col * 4);
    }
    uint32_t xdst = smb + X_OFF + buf * 4096;
    #pragma unroll
    for (int i = 0; i < 2; i++) {
        int idx = i * 128 + tid;
        int j = idx >> 6, col = idx & 63;
        cp16(xdst + idx * 16, g_att + (size_t)bj[j] * C_ + k0 + col * 4);
    }
    cp_commit();
}

// ---------------------------------------------------------------------------
// One pass: 16 W rows x 4 samples/warp. NBUF=3, ONE barrier per stage,
// 2-stage lookahead. WAR chain: issue(k+2) writes buf (k-1)%3, whose readers
// (stage k-1) all passed barrier(k) before issue(k+2) executes.
// ---------------------------------------------------------------------------
__device__ __forceinline__ void run_pass(uint32_t smb, char* sm,
                                         const float* __restrict__ Wg,
                                         int tid, int lane, int warp,
                                         const int* bj,
                                         int a0c, int a0nom, int d,
                                         const float* __restrict__ bias,
                                         float* __restrict__ out)
{
    unsigned long long acc[4][4];
    #pragma unroll
    for (int r = 0; r < 4; r++)
        #pragma unroll
        for (int j = 0; j < 4; j++) acc[r][j] = 0ull;

    // Group-entry barrier: issue(1) below rewrites buf1 while stragglers of
    // the PREVIOUS group may still be computing stage 7 from buf1 (no
    // trailing barrier after last compute). R3/R10 WAR hazard class.
    __syncthreads();

    issue_stage(smb, Wg, 0, tid, bj);
    issue_stage(smb, Wg, 1, tid, bj);

    #pragma unroll
    for (int k = 0; k < NCHUNK; k++) {
        if (k + 1 < NCHUNK) cp_wait<1>(); else cp_wait<0>();
        __syncthreads();                               // stage k visible; WAR ok
        if (k + 2 < NCHUNK) issue_stage(smb, Wg, k + 2, tid, bj);

        const float* Wb = (const float*)(sm + (k % 3) * 16384);
        const float* Xb = (const float*)(sm + X_OFF + (k % 3) * 4096);
        #pragma unroll
        for (int st = 0; st < 2; st++) {               // CK/4 = 64 float4
            int c = lane + st * 32;
            ulonglong2 w[4];
            #pragma unroll
            for (int r = 0; r < 4; r++)
                w[r] = ((const ulonglong2*)(Wb + (warp * 4 + r) * CK))[c];
            #pragma unroll
            for (int j = 0; j < 4; j++) {
                ulonglong2 x = ((const ulonglong2*)(Xb + j * CK))[c];
                #pragma unroll
                for (int r = 0; r < 4; r++) {
                    fma2(acc[r][j], w[r].x, x.x);
                    fma2(acc[r][j], w[r].y, x.y);
                }
            }
        }
    }

    #pragma unroll
    for (int r = 0; r < 4; r++) {
        int a = a0c + warp * 4 + r;
        #pragma unroll
        for (int j = 0; j < 4; j++) {                  // padded j idempotent
            float v = __uint_as_float((unsigned)(acc[r][j] & 0xffffffffu))
                    + __uint_as_float((unsigned)(acc[r][j] >> 32));
            #pragma unroll
            for (int o = 16; o; o >>= 1) v += __shfl_xor_sync(0xffffffffu, v, o);
            if (lane == 0 && a >= a0nom)
                out[(size_t)bj[j] * NA_ + a] = v + bias[(size_t)d * NA_ + a];
        }
    }
}

// ---------------------------------------------------------------------------
// Kernel 2: grouped GEMM. Grid (116, 32); single uniform pass shape.
// ---------------------------------------------------------------------------
__global__ void __launch_bounds__(THREADS, 3) k_gemm(const void* __restrict__ inst_raw,
                                                     const float* __restrict__ W,
                                                     const float* __restrict__ bias,
                                                     float* __restrict__ out)
{
    extern __shared__ char sm[];
    uint32_t smb = smem_u32(sm);
    int* s_list = (int*)(sm + SM_LIST);
    int* s_cnt  = (int*)(sm + SM_CNT);
    int* s_is64 = (int*)(sm + SM_IS64);

    if (threadIdx.x == 0) {
        // Detect int64 vs int32 instance layout (values 0..31 => odd words 0).
        const unsigned* pw = (const unsigned*)inst_raw;
        unsigned orv = 0;
        for (int i = 1; i < 128; i += 2) orv |= pw[i];
        *s_is64 = (orv == 0) ? 1 : 0;
        *s_cnt  = 0;
    }
    __syncthreads();

    int d = blockIdx.y;
    {   // 128 threads scan all 128 instances
        int v = *s_is64 ? (int)((const long long*)inst_raw)[threadIdx.x]
                        : ((const int*)inst_raw)[threadIdx.x];
        if (v == d) {
            int p = atomicAdd(s_cnt, 1);
            s_list[p] = threadIdx.x;
        }
    }
    __syncthreads();

    int m = *s_cnt;
    if (m == 0) return;                                // unused descriptor

    int tid  = threadIdx.x;
    int lane = tid & 31;
    int warp = tid >> 5;
    int a0nom = blockIdx.x * ATILE;
    int a0c   = a0nom > NA_ - ATILE ? NA_ - ATILE : a0nom;
    const float* W0 = W + ((size_t)d * NA_ + a0c) * C_;

    // s_list is written once above and never modified -> bj reads are safe
    // at any point (no cross-pass snapshot hazards).
    for (int mbase = 0; mbase < m; mbase += 4) {
        int mc = m - mbase; if (mc > 4) mc = 4;
        int bj[4];
        #pragma unroll
        for (int j = 0; j < 4; j++)
            bj[j] = s_list[mbase + (j < mc ? j : mc - 1)];

        run_pass(smb, sm, W0, tid, lane, warp, bj, a0c, a0nom, d, bias, out);
    }
}

// ---------------------------------------------------------------------------
// Inputs (metadata order): mask f32[128,1,14,14], features f32[128,2048,14,14],
// instance int[128], W f32[32,1845,2048], b f32[32,1845]. Output f32[128,1845].
// ---------------------------------------------------------------------------
extern "C" void kernel_launch(void* const* d_in, const int* in_sizes, int n_in,
                              void* d_out, int out_size)
{
    const float* mask = (const float*)d_in[0];
    const float* feat = (const float*)d_in[1];
    const void*  inst = d_in[2];
    const float* W    = (const float*)d_in[3];
    const float* bias = (const float*)d_in[4];
    float* out = (float*)d_out;

    int blocks1 = (B_ * C_) / 8;                       // warp per (b,c) row
    k_attend<<<blocks1, 256>>>(mask, feat);

    cudaFuncSetAttribute(k_gemm, cudaFuncAttributeMaxDynamicSharedMemorySize,
                         SM_TOT);
    dim3 g2((NA_ + ATILE - 1) / ATILE, ND_);           // (116, 32)
    k_gemm<<<g2, THREADS, SM_TOT>>>(inst, W, bias, out);
}